// round 7
// baseline (speedup 1.0000x reference)
#include <cuda_runtime.h>
#include <math_constants.h>

// Problem constants
#define B_   64
#define L_   1024
#define D_   64
#define BQ   32          // q rows per CTA
#define BK   64          // keys per tile
#define NTILE (L_ / BK)  // 16
#define PITCH 68         // smem row pitch in floats (conflict-free LDS.128)
#define THREADS 256

// smem layout (floats):
//   sS  [32][1024]            32768
//   sQ  [32][PITCH]            2176
//   sKV [2][64][PITCH]         8704   (K tiles, then reused transposed for V)
#define SMEM_FLOATS (BQ * L_ + BQ * PITCH + 2 * BK * PITCH)

// 0 = mask is 1 byte/element, 1 = mask is 4 bytes/element (int32 or float32)
__device__ int g_mask_w4;

__global__ void detect_mask_kernel(const unsigned* m)
{
    if (threadIdx.x == 0) {
        int w4 = 1;
        for (int i = 0; i < 4096; i++) {
            unsigned v = m[i];
            if (!(v == 0u || v == 1u || v == 0x3F800000u)) { w4 = 0; break; }
        }
        g_mask_w4 = w4;
    }
}

__global__ __launch_bounds__(THREADS, 1)
void attn_fp32_kernel(const float* __restrict__ q,
                      const float* __restrict__ k,
                      const float* __restrict__ v,
                      const void* __restrict__ maskp,
                      float* __restrict__ outO,
                      float* __restrict__ outA)
{
    extern __shared__ float smem[];
    float* sS = smem;                       // [32][1024]
    float* sQ = smem + BQ * L_;             // [32][PITCH]
    float* sKV = sQ + BQ * PITCH;           // [2][64][PITCH]

    const int b  = blockIdx.y;
    const int q0 = blockIdx.x * BQ;
    const int t    = threadIdx.x;
    const int warp = t >> 5;
    const int lane = t & 31;
    const int wm = warp >> 1;               // 0..3 : row group of 8
    const int wn = warp & 1;                // 0..1 : key/col group of 32
    const int row0 = wm * 8;
    const int colw = wn * 32 + lane;        // 0..63 within tile

    const int mask_w4 = g_mask_w4;          // uniform

    const float* qb = q + ((size_t)b * L_ + q0) * D_;
    const float* kb = k + (size_t)b * L_ * D_;
    const float* vb = v + (size_t)b * L_ * D_;
    const size_t mbase = ((size_t)b * L_ + q0) * (size_t)L_;
    const unsigned char* mb8 = (const unsigned char*)maskp + mbase;
    const unsigned*      mb4 = (const unsigned*)maskp + mbase;
    float* oOb = outO + ((size_t)b * L_ + q0) * D_;
    float* oAb = outA + ((size_t)b * L_ + q0) * (size_t)L_;

    // ---- load Q tile (32 x 64) into smem, pitch 68 ----
    #pragma unroll
    for (int p = 0; p < 2; p++) {
        int idx = t + p * THREADS;          // float4 index, 512 total
        int r = idx >> 4, c4 = idx & 15;
        float4 f = ((const float4*)qb)[r * 16 + c4];
        *(float4*)&sQ[r * PITCH + c4 * 4] = f;
    }

    // ---- prefetch K tile 0 ----
    float4 kreg[4];
    #pragma unroll
    for (int p = 0; p < 4; p++) {
        int idx = t + p * THREADS;          // 1024 float4
        int r = idx >> 4, c4 = idx & 15;
        kreg[p] = ((const float4*)kb)[r * 16 + c4];
    }
    #pragma unroll
    for (int p = 0; p < 4; p++) {
        int idx = t + p * THREADS;
        int r = idx >> 4, c4 = idx & 15;
        *(float4*)&sKV[r * PITCH + c4 * 4] = kreg[p];
    }
    __syncthreads();

    // ================= QK^T =================
    for (int kt = 0; kt < NTILE; kt++) {
        const int cur = kt & 1, nxt = cur ^ 1;
        if (kt + 1 < NTILE) {
            #pragma unroll
            for (int p = 0; p < 4; p++) {
                int idx = t + p * THREADS;
                int r = idx >> 4, c4 = idx & 15;
                kreg[p] = ((const float4*)kb)[((kt + 1) * BK + r) * 16 + c4];
            }
        }
        float acc[8];
        #pragma unroll
        for (int r = 0; r < 8; r++) acc[r] = 0.f;

        const float* kp = &sKV[cur * BK * PITCH + colw * PITCH];
        #pragma unroll
        for (int d4 = 0; d4 < 16; d4++) {
            float4 kf = *(const float4*)&kp[d4 * 4];
            #pragma unroll
            for (int r = 0; r < 8; r++) {
                float4 qf = *(const float4*)&sQ[(row0 + r) * PITCH + d4 * 4];
                acc[r] = fmaf(qf.x, kf.x, acc[r]);
                acc[r] = fmaf(qf.y, kf.y, acc[r]);
                acc[r] = fmaf(qf.z, kf.z, acc[r]);
                acc[r] = fmaf(qf.w, kf.w, acc[r]);
            }
        }

        const int g = kt * BK + colw;
        #pragma unroll
        for (int r = 0; r < 8; r++) {
            int rr = row0 + r;
            size_t midx = (size_t)rr * L_ + g;
            bool m = mask_w4 ? (mb4[midx] != 0u) : (mb8[midx] != 0);
            sS[rr * L_ + g] = m ? -CUDART_INF_F : acc[r] * 0.125f;
        }

        if (kt + 1 < NTILE) {
            #pragma unroll
            for (int p = 0; p < 4; p++) {
                int idx = t + p * THREADS;
                int r = idx >> 4, c4 = idx & 15;
                *(float4*)&sKV[nxt * BK * PITCH + r * PITCH + c4 * 4] = kreg[p];
            }
        }
        __syncthreads();
    }

    // ================= softmax (exact, full row in smem) =================
    // each warp owns 4 rows
    for (int rr = 0; rr < 4; rr++) {
        int row = warp * 4 + rr;
        float* srow = &sS[row * L_];
        float mx = -CUDART_INF_F;
        for (int j = lane; j < L_; j += 32) mx = fmaxf(mx, srow[j]);
        #pragma unroll
        for (int o = 16; o; o >>= 1) mx = fmaxf(mx, __shfl_xor_sync(0xFFFFFFFFu, mx, o));

        float sum = 0.f;
        for (int j = lane; j < L_; j += 32) {
            float e = __expf(srow[j] - mx);   // exp(-inf)=0 for masked
            srow[j] = e;
            sum += e;
        }
        #pragma unroll
        for (int o = 16; o; o >>= 1) sum += __shfl_xor_sync(0xFFFFFFFFu, sum, o);
        float inv = 1.f / sum;

        float* arow = &oAb[(size_t)row * L_];
        for (int j = lane; j < L_; j += 32) {
            float pv = srow[j] * inv;
            srow[j] = pv;
            arow[j] = pv;
        }
    }
    __syncthreads();

    // ================= P @ V =================
    // V tiles stored TRANSPOSED in smem: sVt[d][key_local], pitch 68.
    // Then O[r][c] = sum_k P[r][k] * Vt[c][k] — same microkernel shape as QK^T.
    float acc2[8];
    #pragma unroll
    for (int r = 0; r < 8; r++) acc2[r] = 0.f;

    // prefetch V tile 0
    #pragma unroll
    for (int p = 0; p < 4; p++) {
        int idx = t + p * THREADS;
        int r = idx >> 4, c4 = idx & 15;
        kreg[p] = ((const float4*)vb)[r * 16 + c4];
    }
    #pragma unroll
    for (int p = 0; p < 4; p++) {
        int idx = t + p * THREADS;
        int r = idx >> 4, c4 = idx & 15;   // r = key_local, c4*4 = d base
        float4 f = kreg[p];
        float* base = &sKV[0];
        base[(c4 * 4 + 0) * PITCH + r] = f.x;
        base[(c4 * 4 + 1) * PITCH + r] = f.y;
        base[(c4 * 4 + 2) * PITCH + r] = f.z;
        base[(c4 * 4 + 3) * PITCH + r] = f.w;
    }
    __syncthreads();

    for (int kt = 0; kt < NTILE; kt++) {
        const int cur = kt & 1, nxt = cur ^ 1;
        if (kt + 1 < NTILE) {
            #pragma unroll
            for (int p = 0; p < 4; p++) {
                int idx = t + p * THREADS;
                int r = idx >> 4, c4 = idx & 15;
                kreg[p] = ((const float4*)vb)[((kt + 1) * BK + r) * 16 + c4];
            }
        }

        const float* vp = &sKV[cur * BK * PITCH + colw * PITCH];  // colw = output col (d)
        #pragma unroll
        for (int k4 = 0; k4 < 16; k4++) {
            float4 vf = *(const float4*)&vp[k4 * 4];
            #pragma unroll
            for (int r = 0; r < 8; r++) {
                float4 pf = *(const float4*)&sS[(row0 + r) * L_ + kt * BK + k4 * 4];
                acc2[r] = fmaf(pf.x, vf.x, acc2[r]);
                acc2[r] = fmaf(pf.y, vf.y, acc2[r]);
                acc2[r] = fmaf(pf.z, vf.z, acc2[r]);
                acc2[r] = fmaf(pf.w, vf.w, acc2[r]);
            }
        }

        if (kt + 1 < NTILE) {
            #pragma unroll
            for (int p = 0; p < 4; p++) {
                int idx = t + p * THREADS;
                int r = idx >> 4, c4 = idx & 15;
                float4 f = kreg[p];
                float* base = &sKV[nxt * BK * PITCH];
                base[(c4 * 4 + 0) * PITCH + r] = f.x;
                base[(c4 * 4 + 1) * PITCH + r] = f.y;
                base[(c4 * 4 + 2) * PITCH + r] = f.z;
                base[(c4 * 4 + 3) * PITCH + r] = f.w;
            }
        }
        __syncthreads();
    }

    // write O (32 x 64), coalesced per warp-row
    #pragma unroll
    for (int r = 0; r < 8; r++) {
        oOb[(size_t)(row0 + r) * D_ + colw] = acc2[r];
    }
}

extern "C" void kernel_launch(void* const* d_in, const int* in_sizes, int n_in,
                              void* d_out, int out_size)
{
    const float* q = (const float*)d_in[0];
    const float* k = (const float*)d_in[1];
    const float* v = (const float*)d_in[2];
    const void*  mask = d_in[3];

    float* outO = (float*)d_out;                               // (B, Lq, D)
    float* outA = outO + (size_t)B_ * L_ * D_;                 // (B, Lq, Lk)

    const int smem_bytes = SMEM_FLOATS * (int)sizeof(float);   // 174592
    cudaFuncSetAttribute(attn_fp32_kernel,
                         cudaFuncAttributeMaxDynamicSharedMemorySize, smem_bytes);

    detect_mask_kernel<<<1, 32>>>((const unsigned*)mask);

    dim3 grid(L_ / BQ, B_);   // (32, 64)
    attn_fp32_kernel<<<grid, THREADS, smem_bytes>>>(q, k, v, mask, outO, outA);
}

// round 8
// speedup vs baseline: 1.3738x; 1.3738x over previous
#include <cuda_runtime.h>
#include <math_constants.h>
#include <stdint.h>

// Problem constants
#define B_   64
#define L_   1024
#define D_   64
#define BQ   32          // q rows per CTA
#define CH   64          // keys per chunk
#define NCH  (L_ / CH)   // 16
#define THREADS 256

#define SP 1028          // sS pitch (mod 32 == 4 -> conflict-free A-frag loads)
#define QP 68            // Q pitch  (mod 32 == 4 -> conflict-free A-frag loads)
#define VP 72            // buf pitch for V phase (mod 32 == 8 -> conflict-free B-frag loads)
#define KP 68            // K-phase pitch inside buf

// smem (floats): sS[32][1028] | sQh[32][68] | sQl[32][68] | buf[2][64][72]
#define OFF_SQH (BQ * SP)
#define OFF_SQL (OFF_SQH + BQ * QP)
#define OFF_BUF (OFF_SQL + BQ * QP)
#define SMEM_FLOATS (OFF_BUF + 2 * CH * VP)

// 0 = mask is 1 byte/element, 1 = mask is 4 bytes/element (int32 or float32)
__device__ int g_mask_w4;

__global__ void detect_mask_kernel(const unsigned* m)
{
    if (threadIdx.x == 0) {
        int w4 = 1;
        for (int i = 0; i < 4096; i++) {
            unsigned v = m[i];
            if (!(v == 0u || v == 1u || v == 0x3F800000u)) { w4 = 0; break; }
        }
        g_mask_w4 = w4;
    }
}

__device__ __forceinline__ float tf32r(float x) {
    uint32_t u;
    asm("cvt.rna.tf32.f32 %0, %1;" : "=r"(u) : "f"(x));
    return __uint_as_float(u);
}

__device__ __forceinline__ void cp_async16(uint32_t saddr, const void* gaddr) {
    asm volatile("cp.async.cg.shared.global [%0], [%1], 16;" :: "r"(saddr), "l"(gaddr));
}
__device__ __forceinline__ void cp_commit() { asm volatile("cp.async.commit_group;"); }
template<int N> __device__ __forceinline__ void cp_wait() {
    asm volatile("cp.async.wait_group %0;" :: "n"(N));
}

#define MMA_TF32(c, A0, A1, A2, A3, Bb0, Bb1)                                   \
    asm volatile(                                                               \
        "mma.sync.aligned.m16n8k8.row.col.f32.tf32.tf32.f32 "                   \
        "{%0,%1,%2,%3}, {%4,%5,%6,%7}, {%8,%9}, {%0,%1,%2,%3};"                 \
        : "+f"((c)[0]), "+f"((c)[1]), "+f"((c)[2]), "+f"((c)[3])                \
        : "r"(__float_as_uint(A0)), "r"(__float_as_uint(A1)),                   \
          "r"(__float_as_uint(A2)), "r"(__float_as_uint(A3)),                   \
          "r"(__float_as_uint(Bb0)), "r"(__float_as_uint(Bb1)))

__global__ __launch_bounds__(THREADS, 1)
void attn_tf32_kernel(const float* __restrict__ q,
                      const float* __restrict__ k,
                      const float* __restrict__ v,
                      const void* __restrict__ maskp,
                      float* __restrict__ outO,
                      float* __restrict__ outA)
{
    extern __shared__ float smem[];
    float* sS  = smem;
    float* sQh = smem + OFF_SQH;
    float* sQl = smem + OFF_SQL;
    float* buf = smem + OFF_BUF;

    const int b   = blockIdx.y;
    const int q0  = blockIdx.x * BQ;
    const int t    = threadIdx.x;
    const int warp = t >> 5;
    const int lane = t & 31;
    const int gid  = lane >> 2;   // groupID 0..7
    const int tig  = lane & 3;    // thread-in-group 0..3

    const int mask_w4 = g_mask_w4;

    const float* qb = q + ((size_t)b * L_ + q0) * D_;
    const float* kb = k + (size_t)b * L_ * D_;
    const float* vb = v + (size_t)b * L_ * D_;
    const size_t mbase = ((size_t)b * L_ + q0) * (size_t)L_;
    const unsigned char* mb8 = (const unsigned char*)maskp + mbase;
    const unsigned*      mb4 = (const unsigned*)maskp + mbase;
    float* oOb = outO + ((size_t)b * L_ + q0) * D_;
    float* oAb = outA + ((size_t)b * L_ + q0) * (size_t)L_;

    // ---- stage Q hi/lo (32 x 64), pitch 68 ----
    #pragma unroll
    for (int p = 0; p < 2; p++) {
        int idx = t + p * THREADS;         // 512 float4
        int r = idx >> 4, c4 = idx & 15;
        float4 f = ((const float4*)qb)[r * 16 + c4];
        float hx = tf32r(f.x), hy = tf32r(f.y), hz = tf32r(f.z), hw = tf32r(f.w);
        float* dh = &sQh[r * QP + c4 * 4];
        float* dl = &sQl[r * QP + c4 * 4];
        dh[0] = hx; dh[1] = hy; dh[2] = hz; dh[3] = hw;
        dl[0] = tf32r(f.x - hx); dl[1] = tf32r(f.y - hy);
        dl[2] = tf32r(f.z - hz); dl[3] = tf32r(f.w - hw);
    }

    // ================= Phase 1: S = mask(QK^T / 8) =================
    // stage K chunk 0 (64 keys x 64 d), pitch KP, raw fp32
    {
        #pragma unroll
        for (int p = 0; p < 4; p++) {
            int idx = t + p * THREADS;     // 1024 float4
            int r = idx >> 4, c4 = idx & 15;
            uint32_t sa = (uint32_t)__cvta_generic_to_shared(&buf[r * KP + c4 * 4]);
            cp_async16(sa, &kb[r * 64 + c4 * 4]);
        }
        cp_commit();
    }

    for (int c = 0; c < NCH; c++) {
        const int cur = c & 1, nxt = cur ^ 1;
        if (c + 1 < NCH) {
            #pragma unroll
            for (int p = 0; p < 4; p++) {
                int idx = t + p * THREADS;
                int r = idx >> 4, c4 = idx & 15;
                uint32_t sa = (uint32_t)__cvta_generic_to_shared(
                    &buf[nxt * CH * VP + r * KP + c4 * 4]);
                cp_async16(sa, &kb[((c + 1) * CH + r) * 64 + c4 * 4]);
            }
            cp_commit();
            cp_wait<1>();
        } else {
            cp_wait<0>();
        }
        __syncthreads();

        const float* kbuf = &buf[cur * CH * VP];
        const int n0 = warp * 8;           // 8 keys per warp within chunk
        float acc[2][4] = {{0.f,0.f,0.f,0.f},{0.f,0.f,0.f,0.f}};

        #pragma unroll
        for (int ks = 0; ks < 8; ks++) {
            const int k0 = ks * 8;
            // B frags: b0 = K[n0+gid][k0+tig], b1 = col+4
            float br0 = kbuf[(n0 + gid) * KP + k0 + tig];
            float br1 = kbuf[(n0 + gid) * KP + k0 + 4 + tig];
            float bh0 = tf32r(br0), bl0 = tf32r(br0 - bh0);
            float bh1 = tf32r(br1), bl1 = tf32r(br1 - bh1);
            #pragma unroll
            for (int m = 0; m < 2; m++) {
                int r0 = 16 * m + gid;
                float ah0 = sQh[ r0      * QP + k0 + tig];
                float ah1 = sQh[(r0 + 8) * QP + k0 + tig];
                float ah2 = sQh[ r0      * QP + k0 + 4 + tig];
                float ah3 = sQh[(r0 + 8) * QP + k0 + 4 + tig];
                float al0 = sQl[ r0      * QP + k0 + tig];
                float al1 = sQl[(r0 + 8) * QP + k0 + tig];
                float al2 = sQl[ r0      * QP + k0 + 4 + tig];
                float al3 = sQl[(r0 + 8) * QP + k0 + 4 + tig];
                MMA_TF32(acc[m], ah0, ah1, ah2, ah3, bh0, bh1);
                MMA_TF32(acc[m], al0, al1, al2, al3, bh0, bh1);
                MMA_TF32(acc[m], ah0, ah1, ah2, ah3, bl0, bl1);
            }
        }

        // epilogue: scale, mask, store to sS
        #pragma unroll
        for (int m = 0; m < 2; m++) {
            int r0 = 16 * m + gid;
            int g0 = c * CH + n0 + 2 * tig;
            #pragma unroll
            for (int e = 0; e < 4; e++) {
                int row = r0 + (e >> 1) * 8;
                int g   = g0 + (e & 1);
                size_t midx = (size_t)row * L_ + g;
                bool msk = mask_w4 ? (mb4[midx] != 0u) : (mb8[midx] != 0);
                sS[row * SP + g] = msk ? -CUDART_INF_F : acc[m][e] * 0.125f;
            }
        }
        __syncthreads();
    }

    // ================= softmax (exact, full row in smem) =================
    #pragma unroll
    for (int rr = 0; rr < 4; rr++) {
        int row = warp * 4 + rr;
        float* srow = &sS[row * SP];
        float mx = -CUDART_INF_F;
        for (int j = lane; j < L_; j += 32) mx = fmaxf(mx, srow[j]);
        #pragma unroll
        for (int o = 16; o; o >>= 1) mx = fmaxf(mx, __shfl_xor_sync(0xFFFFFFFFu, mx, o));

        float sum = 0.f;
        for (int j = lane; j < L_; j += 32) {
            float e = __expf(srow[j] - mx);
            srow[j] = e;
            sum += e;
        }
        #pragma unroll
        for (int o = 16; o; o >>= 1) sum += __shfl_xor_sync(0xFFFFFFFFu, sum, o);
        float inv = 1.f / sum;

        float* arow = &oAb[(size_t)row * L_];
        for (int j = lane; j < L_; j += 32) {
            float pv = srow[j] * inv;
            srow[j] = pv;
            arow[j] = pv;
        }
    }
    __syncthreads();

    // ================= Phase 2: O = P @ V =================
    // stage V chunk 0 (64 keys x 64 d), pitch VP, raw fp32
    {
        #pragma unroll
        for (int p = 0; p < 4; p++) {
            int idx = t + p * THREADS;
            int r = idx >> 4, c4 = idx & 15;
            uint32_t sa = (uint32_t)__cvta_generic_to_shared(&buf[r * VP + c4 * 4]);
            cp_async16(sa, &vb[r * 64 + c4 * 4]);
        }
        cp_commit();
    }

    const int n0v = warp * 8;              // 8 output d-cols per warp
    float acc2[2][4] = {{0.f,0.f,0.f,0.f},{0.f,0.f,0.f,0.f}};

    for (int c = 0; c < NCH; c++) {
        const int cur = c & 1, nxt = cur ^ 1;
        if (c + 1 < NCH) {
            #pragma unroll
            for (int p = 0; p < 4; p++) {
                int idx = t + p * THREADS;
                int r = idx >> 4, c4 = idx & 15;
                uint32_t sa = (uint32_t)__cvta_generic_to_shared(
                    &buf[nxt * CH * VP + r * VP + c4 * 4]);
                cp_async16(sa, &vb[((c + 1) * CH + r) * 64 + c4 * 4]);
            }
            cp_commit();
            cp_wait<1>();
        } else {
            cp_wait<0>();
        }
        __syncthreads();

        const float* vbuf = &buf[cur * CH * VP];

        #pragma unroll
        for (int ks = 0; ks < 8; ks++) {
            const int k0c = ks * 8;               // key offset within chunk
            const int kg  = c * CH + k0c;         // global key (sS col)
            // B frags: b0 = V[k0c+tig][n0v+gid], b1 = row+4
            float br0 = vbuf[(k0c + tig) * VP + n0v + gid];
            float br1 = vbuf[(k0c + 4 + tig) * VP + n0v + gid];
            float bh0 = tf32r(br0), bl0 = tf32r(br0 - bh0);
            float bh1 = tf32r(br1), bl1 = tf32r(br1 - bh1);
            #pragma unroll
            for (int m = 0; m < 2; m++) {
                int r0 = 16 * m + gid;
                float a0 = tf32r(sS[ r0      * SP + kg + tig]);
                float a1 = tf32r(sS[(r0 + 8) * SP + kg + tig]);
                float a2 = tf32r(sS[ r0      * SP + kg + 4 + tig]);
                float a3 = tf32r(sS[(r0 + 8) * SP + kg + 4 + tig]);
                MMA_TF32(acc2[m], a0, a1, a2, a3, bh0, bh1);
                MMA_TF32(acc2[m], a0, a1, a2, a3, bl0, bl1);
            }
        }
        __syncthreads();
    }

    // ---- write O (32 x 64) ----
    #pragma unroll
    for (int m = 0; m < 2; m++) {
        int r0 = 16 * m + gid;
        int c0 = n0v + 2 * tig;
        oOb[(size_t)r0 * D_ + c0]           = acc2[m][0];
        oOb[(size_t)r0 * D_ + c0 + 1]       = acc2[m][1];
        oOb[(size_t)(r0 + 8) * D_ + c0]     = acc2[m][2];
        oOb[(size_t)(r0 + 8) * D_ + c0 + 1] = acc2[m][3];
    }
}

extern "C" void kernel_launch(void* const* d_in, const int* in_sizes, int n_in,
                              void* d_out, int out_size)
{
    const float* q = (const float*)d_in[0];
    const float* k = (const float*)d_in[1];
    const float* v = (const float*)d_in[2];
    const void*  mask = d_in[3];

    float* outO = (float*)d_out;                               // (B, Lq, D)
    float* outA = outO + (size_t)B_ * L_ * D_;                 // (B, Lq, Lk)

    const int smem_bytes = SMEM_FLOATS * (int)sizeof(float);   // 185856
    cudaFuncSetAttribute(attn_tf32_kernel,
                         cudaFuncAttributeMaxDynamicSharedMemorySize, smem_bytes);

    detect_mask_kernel<<<1, 32>>>((const unsigned*)mask);

    dim3 grid(L_ / BQ, B_);   // (32, 64)
    attn_tf32_kernel<<<grid, THREADS, smem_bytes>>>(q, k, v, mask, outO, outA);
}

// round 9
// speedup vs baseline: 1.6142x; 1.1751x over previous
#include <cuda_runtime.h>
#include <math_constants.h>
#include <stdint.h>

// Problem constants
#define B_   64
#define L_   1024
#define D_   64
#define BQ   32          // q rows per CTA
#define CH   128         // keys per chunk
#define NCH  (L_ / CH)   // 8
#define THREADS 512

#define SP   1028        // sS pitch (mod 32 == 4 -> conflict-free scalar frag loads)
#define QP2  136         // Q pitch, hi/lo interleaved (mod 32 == 8 -> conflict-free LDS.64)
#define KP   68          // K-phase pitch inside buf (mod 32 == 4)
#define VP   72          // V-phase pitch inside buf (mod 32 == 8)
#define BUFSZ (CH * VP)  // 9216 floats per buffer

// smem (floats): sS[32][1028] | sQ[32][136] (hi/lo interleaved) | buf[2][BUFSZ] | sSum[32] | sInv[32]
#define OFF_SQ  (BQ * SP)
#define OFF_BUF (OFF_SQ + BQ * QP2)
#define OFF_SUM (OFF_BUF + 2 * BUFSZ)
#define OFF_INV (OFF_SUM + 32)
#define SMEM_FLOATS (OFF_INV + 32)

// 0 = mask is 1 byte/element, 1 = mask is 4 bytes/element (int32 or float32)
__device__ int g_mask_w4;

__global__ void detect_mask_kernel(const unsigned* m)
{
    if (threadIdx.x == 0) {
        int w4 = 1;
        for (int i = 0; i < 4096; i++) {
            unsigned v = m[i];
            if (!(v == 0u || v == 1u || v == 0x3F800000u)) { w4 = 0; break; }
        }
        g_mask_w4 = w4;
    }
}

__device__ __forceinline__ float tf32r(float x) {
    uint32_t u;
    asm("cvt.rna.tf32.f32 %0, %1;" : "=r"(u) : "f"(x));
    return __uint_as_float(u);
}

__device__ __forceinline__ void cp_async16(uint32_t saddr, const void* gaddr) {
    asm volatile("cp.async.cg.shared.global [%0], [%1], 16;" :: "r"(saddr), "l"(gaddr));
}
__device__ __forceinline__ void cp_commit() { asm volatile("cp.async.commit_group;"); }
template<int N> __device__ __forceinline__ void cp_wait() {
    asm volatile("cp.async.wait_group %0;" :: "n"(N));
}

#define MMA_TF32(c, A0, A1, A2, A3, Bb0, Bb1)                                   \
    asm volatile(                                                               \
        "mma.sync.aligned.m16n8k8.row.col.f32.tf32.tf32.f32 "                   \
        "{%0,%1,%2,%3}, {%4,%5,%6,%7}, {%8,%9}, {%0,%1,%2,%3};"                 \
        : "+f"((c)[0]), "+f"((c)[1]), "+f"((c)[2]), "+f"((c)[3])                \
        : "r"(__float_as_uint(A0)), "r"(__float_as_uint(A1)),                   \
          "r"(__float_as_uint(A2)), "r"(__float_as_uint(A3)),                   \
          "r"(__float_as_uint(Bb0)), "r"(__float_as_uint(Bb1)))

__global__ __launch_bounds__(THREADS, 1)
void attn_tf32_kernel(const float* __restrict__ q,
                      const float* __restrict__ k,
                      const float* __restrict__ v,
                      const void* __restrict__ maskp,
                      float* __restrict__ outO,
                      float* __restrict__ outA)
{
    extern __shared__ float smem[];
    float* sS   = smem;
    float* sQ   = smem + OFF_SQ;
    float* buf  = smem + OFF_BUF;
    float* sSum = smem + OFF_SUM;
    float* sInv = smem + OFF_INV;

    const int b   = blockIdx.y;
    const int q0  = blockIdx.x * BQ;
    const int t    = threadIdx.x;
    const int warp = t >> 5;
    const int lane = t & 31;
    const int gid  = lane >> 2;   // groupID 0..7
    const int tig  = lane & 3;    // thread-in-group 0..3

    const int mask_w4 = g_mask_w4;

    const float* qb = q + ((size_t)b * L_ + q0) * D_;
    const float* kb = k + (size_t)b * L_ * D_;
    const float* vb = v + (size_t)b * L_ * D_;
    const size_t mbase = ((size_t)b * L_ + q0) * (size_t)L_;
    const unsigned char* mb8 = (const unsigned char*)maskp + mbase;
    const unsigned*      mb4 = (const unsigned*)maskp + mbase;
    float* oOb = outO + ((size_t)b * L_ + q0) * D_;
    float* oAb = outA + ((size_t)b * L_ + q0) * (size_t)L_;

    if (t < 32) sSum[t] = 0.f;

    // ---- stage Q (32 x 64): scale by 1/8 (exact), split hi/lo interleaved ----
    {
        int r = t >> 4, c4 = t & 15;                 // 512 float4 = whole tile
        float4 f = ((const float4*)qb)[t];
        f.x *= 0.125f; f.y *= 0.125f; f.z *= 0.125f; f.w *= 0.125f;
        float hx = tf32r(f.x), hy = tf32r(f.y), hz = tf32r(f.z), hw = tf32r(f.w);
        float4 lo4 = make_float4(hx, f.x - hx, hy, f.y - hy);
        float4 hi4 = make_float4(hz, f.z - hz, hw, f.w - hw);
        lo4.y = tf32r(lo4.y); lo4.w = tf32r(lo4.w);
        hi4.y = tf32r(hi4.y); hi4.w = tf32r(hi4.w);
        float* dst = &sQ[r * QP2 + 8 * c4];
        *(float4*)dst       = lo4;   // {hx,lx,hy,ly}
        *(float4*)(dst + 4) = hi4;   // {hz,lz,hw,lw}
    }

    // ---- prefetch K chunk 0 (128 keys x 64 d, pitch KP) ----
    #pragma unroll
    for (int p = 0; p < 4; p++) {
        int idx = t + p * THREADS;                   // 2048 float4
        int r = idx >> 4, c4 = idx & 15;
        uint32_t sa = (uint32_t)__cvta_generic_to_shared(&buf[r * KP + c4 * 4]);
        cp_async16(sa, &kb[r * 64 + c4 * 4]);
    }
    cp_commit();

    // ================= Phase 1: sS = exp(mask(QK^T / 8)) + row sums =================
    const int mw = warp & 1;           // m-group: rows mw*16 .. +15
    const int nw = warp >> 1;          // n-group: keys nw*16 .. +15 within chunk
    const int r0 = mw * 16;
    const int n0 = nw * 16;

    for (int c = 0; c < NCH; c++) {
        const int cur = c & 1, nxt = cur ^ 1;
        if (c + 1 < NCH) {
            #pragma unroll
            for (int p = 0; p < 4; p++) {
                int idx = t + p * THREADS;
                int r = idx >> 4, c4 = idx & 15;
                uint32_t sa = (uint32_t)__cvta_generic_to_shared(
                    &buf[nxt * BUFSZ + r * KP + c4 * 4]);
                cp_async16(sa, &kb[((c + 1) * CH + r) * 64 + c4 * 4]);
            }
            cp_commit();
            cp_wait<1>();
        } else {
            cp_wait<0>();
        }
        __syncthreads();

        const float* kbuf = &buf[cur * BUFSZ];
        float acc[2][4] = {{0.f,0.f,0.f,0.f},{0.f,0.f,0.f,0.f}};

        #pragma unroll
        for (int ks = 0; ks < 8; ks++) {
            const int k0 = ks * 8;
            float2 A0 = *(const float2*)&sQ[(r0 + gid)     * QP2 + 2 * (k0 + tig)];
            float2 A1 = *(const float2*)&sQ[(r0 + 8 + gid) * QP2 + 2 * (k0 + tig)];
            float2 A2 = *(const float2*)&sQ[(r0 + gid)     * QP2 + 2 * (k0 + 4 + tig)];
            float2 A3 = *(const float2*)&sQ[(r0 + 8 + gid) * QP2 + 2 * (k0 + 4 + tig)];
            #pragma unroll
            for (int j = 0; j < 2; j++) {
                const float* kr = &kbuf[(n0 + 8 * j + gid) * KP + k0 + tig];
                float br0 = kr[0], br1 = kr[4];
                float bh0 = tf32r(br0), bl0 = tf32r(br0 - bh0);
                float bh1 = tf32r(br1), bl1 = tf32r(br1 - bh1);
                MMA_TF32(acc[j], A0.x, A1.x, A2.x, A3.x, bh0, bh1);
                MMA_TF32(acc[j], A0.y, A1.y, A2.y, A3.y, bh0, bh1);
                MMA_TF32(acc[j], A0.x, A1.x, A2.x, A3.x, bl0, bl1);
            }
        }

        // epilogue: mask -> exp -> store sS (unnormalized), accumulate row sums
        float s_lo = 0.f, s_hi = 0.f;
        #pragma unroll
        for (int j = 0; j < 2; j++) {
            int colb = c * CH + n0 + 8 * j + 2 * tig;
            #pragma unroll
            for (int e = 0; e < 4; e++) {
                int row = r0 + gid + (e >> 1) * 8;
                int g   = colb + (e & 1);
                unsigned midx = (unsigned)row * L_ + (unsigned)g;
                bool msk = mask_w4 ? (mb4[midx] != 0u) : (mb8[midx] != 0);
                float ex = msk ? 0.f : __expf(acc[j][e]);
                sS[row * SP + g] = ex;
                if (e < 2) s_lo += ex; else s_hi += ex;
            }
        }
        s_lo += __shfl_xor_sync(0xFFFFFFFFu, s_lo, 1);
        s_lo += __shfl_xor_sync(0xFFFFFFFFu, s_lo, 2);
        s_hi += __shfl_xor_sync(0xFFFFFFFFu, s_hi, 1);
        s_hi += __shfl_xor_sync(0xFFFFFFFFu, s_hi, 2);
        if (tig == 0) {
            atomicAdd(&sSum[r0 + gid],     s_lo);
            atomicAdd(&sSum[r0 + 8 + gid], s_hi);
        }
        __syncthreads();
    }

    // row reciprocals
    if (t < 32) sInv[t] = 1.f / sSum[t];

    // ---- prefetch V chunk 0 (pitch VP) while attn is written ----
    #pragma unroll
    for (int p = 0; p < 4; p++) {
        int idx = t + p * THREADS;
        int r = idx >> 4, c4 = idx & 15;
        uint32_t sa = (uint32_t)__cvta_generic_to_shared(&buf[r * VP + c4 * 4]);
        cp_async16(sa, &vb[r * 64 + c4 * 4]);
    }
    cp_commit();
    __syncthreads();   // sInv visible; K-phase buf reads done before V overwrite was issued above
                       // (last K chunk consumed before this point; staging races only with sS/attn work)

    // ---- write normalized attn (sS stays unnormalized for PV) ----
    #pragma unroll
    for (int rr = 0; rr < 2; rr++) {
        int row = warp * 2 + rr;
        float inv = sInv[row];
        const float* srow = &sS[row * SP];
        float* arow = &oAb[(size_t)row * L_];
        for (int j = lane; j < L_; j += 32)
            arow[j] = srow[j] * inv;
    }

    // ================= Phase 2: O = P @ V (single-pass tf32) =================
    const int kw  = warp >> 3;         // 0/1: k-half within chunk (ks 0-7 / 8-15)
    const int nw2 = (warp >> 1) & 3;   // 4 d-col groups of 16
    const int r0v = mw * 16;
    const int n0v = nw2 * 16;
    const int ksb = kw * 8;
    float acc2[2][4] = {{0.f,0.f,0.f,0.f},{0.f,0.f,0.f,0.f}};

    for (int c = 0; c < NCH; c++) {
        const int cur = c & 1, nxt = cur ^ 1;
        if (c + 1 < NCH) {
            #pragma unroll
            for (int p = 0; p < 4; p++) {
                int idx = t + p * THREADS;
                int r = idx >> 4, c4 = idx & 15;
                uint32_t sa = (uint32_t)__cvta_generic_to_shared(
                    &buf[nxt * BUFSZ + r * VP + c4 * 4]);
                cp_async16(sa, &vb[((c + 1) * CH + r) * 64 + c4 * 4]);
            }
            cp_commit();
            cp_wait<1>();
        } else {
            cp_wait<0>();
        }
        __syncthreads();

        const float* vbuf = &buf[cur * BUFSZ];

        #pragma unroll
        for (int ks = 0; ks < 8; ks++) {
            const int kc = (ksb + ks) * 8;          // key offset within chunk
            const int kg = c * CH + kc;             // global key (sS col)
            float a0 = tf32r(sS[(r0v + gid)     * SP + kg + tig]);
            float a1 = tf32r(sS[(r0v + 8 + gid) * SP + kg + tig]);
            float a2 = tf32r(sS[(r0v + gid)     * SP + kg + 4 + tig]);
            float a3 = tf32r(sS[(r0v + 8 + gid) * SP + kg + 4 + tig]);
            #pragma unroll
            for (int j = 0; j < 2; j++) {
                float br0 = vbuf[(kc + tig)     * VP + n0v + 8 * j + gid];
                float br1 = vbuf[(kc + 4 + tig) * VP + n0v + 8 * j + gid];
                float bh0 = tf32r(br0), bh1 = tf32r(br1);
                MMA_TF32(acc2[j], a0, a1, a2, a3, bh0, bh1);
            }
        }
        __syncthreads();
    }

    // ---- reduce k-halves via smem scratch (reuse sQ), scale by 1/sum, write O ----
    float* scr = sQ;   // [32][64]
    if (kw == 1) {
        #pragma unroll
        for (int j = 0; j < 2; j++) {
            #pragma unroll
            for (int e = 0; e < 4; e++) {
                int row = r0v + gid + (e >> 1) * 8;
                int col = n0v + 8 * j + 2 * tig + (e & 1);
                scr[row * 64 + col] = acc2[j][e];
            }
        }
    }
    __syncthreads();
    if (kw == 0) {
        #pragma unroll
        for (int j = 0; j < 2; j++) {
            #pragma unroll
            for (int e = 0; e < 4; e++) {
                int row = r0v + gid + (e >> 1) * 8;
                int col = n0v + 8 * j + 2 * tig + (e & 1);
                float o = (acc2[j][e] + scr[row * 64 + col]) * sInv[row];
                oOb[(size_t)row * D_ + col] = o;
            }
        }
    }
}

extern "C" void kernel_launch(void* const* d_in, const int* in_sizes, int n_in,
                              void* d_out, int out_size)
{
    const float* q = (const float*)d_in[0];
    const float* k = (const float*)d_in[1];
    const float* v = (const float*)d_in[2];
    const void*  mask = d_in[3];

    float* outO = (float*)d_out;                               // (B, Lq, D)
    float* outA = outO + (size_t)B_ * L_ * D_;                 // (B, Lq, Lk)

    const int smem_bytes = SMEM_FLOATS * (int)sizeof(float);   // ~223 KB
    cudaFuncSetAttribute(attn_tf32_kernel,
                         cudaFuncAttributeMaxDynamicSharedMemorySize, smem_bytes);

    detect_mask_kernel<<<1, 32>>>((const unsigned*)mask);

    dim3 grid(L_ / BQ, B_);   // (32, 64)
    attn_tf32_kernel<<<grid, THREADS, smem_bytes>>>(q, k, v, mask, outO, outA);
}

// round 13
// speedup vs baseline: 1.8956x; 1.1743x over previous
#include <cuda_runtime.h>
#include <math_constants.h>
#include <stdint.h>

// Problem constants
#define B_   64
#define L_   1024
#define D_   64
#define BQ   16          // q rows per CTA
#define CH   64          // keys per chunk
#define NCH  (L_ / CH)   // 16
#define THREADS 256

#define SP   1028        // sS pitch (mod 32 == 4 -> conflict-free frag loads)
#define QP2  136         // Q pitch, hi/lo interleaved (mod 32 == 8 -> conflict-free LDS.64)
#define KP   68          // K-phase pitch inside buf (mod 32 == 4)
#define VP   72          // V-phase pitch inside buf (mod 32 == 8)
#define BUFSZ (CH * VP)  // 4608 floats per buffer

// smem (floats): sS[16][1028] | sQ[16][136] | buf[2][BUFSZ] | sSum[16] | sInv[16]
#define OFF_SQ  (BQ * SP)
#define OFF_BUF (OFF_SQ + BQ * QP2)
#define OFF_SUM (OFF_BUF + 2 * BUFSZ)
#define OFF_INV (OFF_SUM + 16)
#define SMEM_FLOATS (OFF_INV + 16)      // 27872 floats = 111488 B -> 2 CTAs/SM

// 0 = mask is 1 byte/element, 1 = mask is 4 bytes/element (int32 or float32)
__device__ int g_mask_w4;

__global__ void detect_mask_kernel(const unsigned* m)
{
    __shared__ int ok;
    if (threadIdx.x == 0) ok = 1;
    __syncthreads();
    #pragma unroll
    for (int p = 0; p < 16; p++) {
        unsigned v = m[threadIdx.x + p * 256];
        if (!(v == 0u || v == 1u || v == 0x3F800000u)) ok = 0;
    }
    __syncthreads();
    if (threadIdx.x == 0) g_mask_w4 = ok;
}

__device__ __forceinline__ float tf32r(float x) {
    uint32_t u;
    asm("cvt.rna.tf32.f32 %0, %1;" : "=r"(u) : "f"(x));
    return __uint_as_float(u);
}

__device__ __forceinline__ void cp_async16(uint32_t saddr, const void* gaddr) {
    asm volatile("cp.async.cg.shared.global [%0], [%1], 16;" :: "r"(saddr), "l"(gaddr));
}
__device__ __forceinline__ void cp_commit() { asm volatile("cp.async.commit_group;"); }
template<int N> __device__ __forceinline__ void cp_wait() {
    asm volatile("cp.async.wait_group %0;" :: "n"(N));
}

#define MMA_TF32(c, A0, A1, A2, A3, Bb0, Bb1)                                   \
    asm volatile(                                                               \
        "mma.sync.aligned.m16n8k8.row.col.f32.tf32.tf32.f32 "                   \
        "{%0,%1,%2,%3}, {%4,%5,%6,%7}, {%8,%9}, {%0,%1,%2,%3};"                 \
        : "+f"((c)[0]), "+f"((c)[1]), "+f"((c)[2]), "+f"((c)[3])                \
        : "r"(__float_as_uint(A0)), "r"(__float_as_uint(A1)),                   \
          "r"(__float_as_uint(A2)), "r"(__float_as_uint(A3)),                   \
          "r"(__float_as_uint(Bb0)), "r"(__float_as_uint(Bb1)))

__global__ __launch_bounds__(THREADS, 2)
void attn_tf32_kernel(const float* __restrict__ q,
                      const float* __restrict__ k,
                      const float* __restrict__ v,
                      const void* __restrict__ maskp,
                      float* __restrict__ outO,
                      float* __restrict__ outA)
{
    extern __shared__ float smem[];
    float* sS   = smem;
    float* sQ   = smem + OFF_SQ;
    float* buf  = smem + OFF_BUF;
    float* sSum = smem + OFF_SUM;
    float* sInv = smem + OFF_INV;

    const int b   = blockIdx.y;
    const int q0  = blockIdx.x * BQ;
    const int t    = threadIdx.x;
    const int warp = t >> 5;
    const int lane = t & 31;
    const int gid  = lane >> 2;   // groupID 0..7
    const int tig  = lane & 3;    // thread-in-group 0..3

    const int mask_w4 = g_mask_w4;

    const float* qb = q + ((size_t)b * L_ + q0) * D_;
    const float* kb = k + (size_t)b * L_ * D_;
    const float* vb = v + (size_t)b * L_ * D_;
    const size_t mbase = ((size_t)b * L_ + q0) * (size_t)L_;
    const unsigned char* mb8 = (const unsigned char*)maskp + mbase;
    const unsigned*      mb4 = (const unsigned*)maskp + mbase;
    float* oOb = outO + ((size_t)b * L_ + q0) * D_;
    float* oAb = outA + ((size_t)b * L_ + q0) * (size_t)L_;

    if (t < 16) sSum[t] = 0.f;

    // ---- stage Q (16 x 64): scale by 1/8 (exact), split hi/lo interleaved ----
    {
        int r = t >> 4, c4 = t & 15;                 // 256 float4 = whole tile
        float4 f = ((const float4*)qb)[t];
        f.x *= 0.125f; f.y *= 0.125f; f.z *= 0.125f; f.w *= 0.125f;
        float hx = tf32r(f.x), hy = tf32r(f.y), hz = tf32r(f.z), hw = tf32r(f.w);
        float4 lo4 = make_float4(hx, tf32r(f.x - hx), hy, tf32r(f.y - hy));
        float4 hi4 = make_float4(hz, tf32r(f.z - hz), hw, tf32r(f.w - hw));
        float* dst = &sQ[r * QP2 + 8 * c4];
        *(float4*)dst       = lo4;   // {hx,lx,hy,ly}
        *(float4*)(dst + 4) = hi4;   // {hz,lz,hw,lw}
    }

    // ---- prefetch K chunk 0 (64 keys x 64 d, pitch KP) ----
    #pragma unroll
    for (int p = 0; p < 4; p++) {
        int idx = t + p * THREADS;                   // 1024 float4
        int r = idx >> 4, c4 = idx & 15;
        uint32_t sa = (uint32_t)__cvta_generic_to_shared(&buf[r * KP + c4 * 4]);
        cp_async16(sa, &kb[r * 64 + c4 * 4]);
    }
    cp_commit();

    // ================= Phase 1: sS = exp(mask(QK^T / 8)) + row sums =================
    const int n0 = warp * 8;       // each warp owns 8 keys per chunk (m16n8 tile)

    for (int c = 0; c < NCH; c++) {
        const int cur = c & 1, nxt = cur ^ 1;
        if (c + 1 < NCH) {
            #pragma unroll
            for (int p = 0; p < 4; p++) {
                int idx = t + p * THREADS;
                int r = idx >> 4, c4 = idx & 15;
                uint32_t sa = (uint32_t)__cvta_generic_to_shared(
                    &buf[nxt * BUFSZ + r * KP + c4 * 4]);
                cp_async16(sa, &kb[((c + 1) * CH + r) * 64 + c4 * 4]);
            }
            cp_commit();
            cp_wait<1>();
        } else {
            cp_wait<0>();
        }
        __syncthreads();

        const float* kbuf = &buf[cur * BUFSZ];
        float acc[4] = {0.f, 0.f, 0.f, 0.f};

        #pragma unroll
        for (int ks = 0; ks < 8; ks++) {
            const int k0 = ks * 8;
            float2 A0 = *(const float2*)&sQ[ gid      * QP2 + 2 * (k0 + tig)];
            float2 A1 = *(const float2*)&sQ[(gid + 8) * QP2 + 2 * (k0 + tig)];
            float2 A2 = *(const float2*)&sQ[ gid      * QP2 + 2 * (k0 + 4 + tig)];
            float2 A3 = *(const float2*)&sQ[(gid + 8) * QP2 + 2 * (k0 + 4 + tig)];
            const float* kr = &kbuf[(n0 + gid) * KP + k0 + tig];
            float br0 = kr[0], br1 = kr[4];
            float bh0 = tf32r(br0), bl0 = tf32r(br0 - bh0);
            float bh1 = tf32r(br1), bl1 = tf32r(br1 - bh1);
            MMA_TF32(acc, A0.x, A1.x, A2.x, A3.x, bh0, bh1);
            MMA_TF32(acc, A0.y, A1.y, A2.y, A3.y, bh0, bh1);
            MMA_TF32(acc, A0.x, A1.x, A2.x, A3.x, bl0, bl1);
        }

        // epilogue: mask -> exp -> store sS tf32-rounded (unnormalized), row sums
        {
            float s_lo = 0.f, s_hi = 0.f;
            float st[4];
            #pragma unroll
            for (int e = 0; e < 4; e++) {
                int row = gid + (e >> 1) * 8;
                int g   = c * CH + n0 + 2 * tig + (e & 1);
                unsigned midx = (unsigned)row * L_ + (unsigned)g;
                bool msk = mask_w4 ? (mb4[midx] != 0u) : (mb8[midx] != 0);
                float ex = msk ? 0.f : __expf(acc[e]);
                st[e] = tf32r(ex);
                if (e < 2) s_lo += ex; else s_hi += ex;
            }
            int colb = c * CH + n0 + 2 * tig;
            *(float2*)&sS[ gid      * SP + colb] = make_float2(st[0], st[1]);
            *(float2*)&sS[(gid + 8) * SP + colb] = make_float2(st[2], st[3]);

            s_lo += __shfl_xor_sync(0xFFFFFFFFu, s_lo, 1);
            s_lo += __shfl_xor_sync(0xFFFFFFFFu, s_lo, 2);
            s_hi += __shfl_xor_sync(0xFFFFFFFFu, s_hi, 1);
            s_hi += __shfl_xor_sync(0xFFFFFFFFu, s_hi, 2);
            if (tig == 0) {
                atomicAdd(&sSum[gid],     s_lo);
                atomicAdd(&sSum[gid + 8], s_hi);
            }
        }
        __syncthreads();
    }

    // row reciprocals
    if (t < 16) sInv[t] = 1.f / sSum[t];

    // ---- prefetch V chunk 0 (pitch VP); overlaps with attn write below ----
    #pragma unroll
    for (int p = 0; p < 4; p++) {
        int idx = t + p * THREADS;
        int r = idx >> 4, c4 = idx & 15;
        uint32_t sa = (uint32_t)__cvta_generic_to_shared(&buf[r * VP + c4 * 4]);
        cp_async16(sa, &vb[r * 64 + c4 * 4]);
    }
    cp_commit();
    __syncthreads();   // sInv visible

    // ---- write normalized attn (sS stays unnormalized for PV) ----
    #pragma unroll
    for (int rr = 0; rr < 2; rr++) {
        int row = warp * 2 + rr;
        float inv = sInv[row];
        const float* srow = &sS[row * SP];
        float* arow = &oAb[(size_t)row * L_];
        for (int j = lane; j < L_; j += 32)
            arow[j] = srow[j] * inv;
    }

    // ================= Phase 2: O = P @ V (single-pass tf32, m16n8) =================
    const int n0v = warp * 8;          // each warp owns 8 output d-cols, full k
    float acc2[4] = {0.f, 0.f, 0.f, 0.f};

    for (int c = 0; c < NCH; c++) {
        const int cur = c & 1, nxt = cur ^ 1;
        if (c + 1 < NCH) {
            #pragma unroll
            for (int p = 0; p < 4; p++) {
                int idx = t + p * THREADS;
                int r = idx >> 4, c4 = idx & 15;
                uint32_t sa = (uint32_t)__cvta_generic_to_shared(
                    &buf[nxt * BUFSZ + r * VP + c4 * 4]);
                cp_async16(sa, &vb[((c + 1) * CH + r) * 64 + c4 * 4]);
            }
            cp_commit();
            cp_wait<1>();
        } else {
            cp_wait<0>();
        }
        __syncthreads();

        const float* vbuf = &buf[cur * BUFSZ];

        #pragma unroll
        for (int ks = 0; ks < 8; ks++) {
            const int kc = ks * 8;                  // key offset within chunk
            const int kg = c * CH + kc;             // global key (sS col)
            float a0 = sS[ gid      * SP + kg + tig];       // pre-rounded tf32
            float a1 = sS[(gid + 8) * SP + kg + tig];
            float a2 = sS[ gid      * SP + kg + 4 + tig];
            float a3 = sS[(gid + 8) * SP + kg + 4 + tig];
            float br0 = vbuf[(kc + tig)     * VP + n0v + gid];
            float br1 = vbuf[(kc + 4 + tig) * VP + n0v + gid];
            float bh0 = tf32r(br0), bh1 = tf32r(br1);
            MMA_TF32(acc2, a0, a1, a2, a3, bh0, bh1);
        }
        __syncthreads();
    }

    // ---- scale by 1/sum, write O (each warp owns its cols; no reduce) ----
    #pragma unroll
    for (int e = 0; e < 4; e++) {
        int row = gid + (e >> 1) * 8;
        int col = n0v + 2 * tig + (e & 1);
        oOb[(size_t)row * D_ + col] = acc2[e] * sInv[row];
    }
}

extern "C" void kernel_launch(void* const* d_in, const int* in_sizes, int n_in,
                              void* d_out, int out_size)
{
    const float* q = (const float*)d_in[0];
    const float* k = (const float*)d_in[1];
    const float* v = (const float*)d_in[2];
    const void*  mask = d_in[3];

    float* outO = (float*)d_out;                               // (B, Lq, D)
    float* outA = outO + (size_t)B_ * L_ * D_;                 // (B, Lq, Lk)

    const int smem_bytes = SMEM_FLOATS * (int)sizeof(float);   // 111488 B
    cudaFuncSetAttribute(attn_tf32_kernel,
                         cudaFuncAttributeMaxDynamicSharedMemorySize, smem_bytes);

    detect_mask_kernel<<<1, 256>>>((const unsigned*)mask);

    dim3 grid(L_ / BQ, B_);   // (64, 64)
    attn_tf32_kernel<<<grid, THREADS, smem_bytes>>>(q, k, v, mask, outO, outA);
}